// round 5
// baseline (speedup 1.0000x reference)
#include <cuda_runtime.h>
#include <cstdint>

// ---------------------------------------------------------------------------
// GMP_34196529611440 : generalized memory polynomial, single fused kernel.
// Round 3: power-basis evaluation from conflict-free padded shared arrays.
//   * shared holds duplicated {p,p},{p2,p2},{p3,p3} and {re,im} per sample,
//     in a stride-5 padded layout -> all LDS are bank-conflict-free.
//   * every polynomial term is an independent fma2 into an accumulator
//     (no Horner chains, no per-thread pp2 register array).
// ---------------------------------------------------------------------------

typedef unsigned long long u64;

__device__ __forceinline__ u64 fma2(u64 a, u64 b, u64 c) {
    u64 d;
    asm("fma.rn.f32x2 %0, %1, %2, %3;" : "=l"(d) : "l"(a), "l"(b), "l"(c));
    return d;
}
__device__ __forceinline__ u64 add2(u64 a, u64 b) {
    u64 d;
    asm("add.rn.f32x2 %0, %1, %2;" : "=l"(d) : "l"(a), "l"(b));
    return d;
}
__device__ __forceinline__ u64 pack2(float x, float y) {
    u64 r;
    asm("mov.b64 %0, {%1, %2};" : "=l"(r) : "f"(x), "f"(y));
    return r;
}
__device__ __forceinline__ void unpack2(u64 v, float& x, float& y) {
    asm("mov.b64 {%0, %1}, %2;" : "=f"(x), "=f"(y) : "l"(v));
}
__device__ __forceinline__ float sqrt_approx(float s) {
    float r;
    asm("sqrt.approx.f32 %0, %1;" : "=f"(r) : "f"(s));
    return r;
}

constexpr int ITER = 4;     // consecutive samples per thread
constexpr int TPB  = 128;
constexpr int SPB  = TPB * ITER;   // 512
constexpr int TILE = SPB + 12;     // halo -5 .. +6
// padded size: pad(i) = i + i/4
constexpr int PTILE = (TILE - 1) + (TILE - 1) / 4 + 1;   // 654

// shared coefficient layout (complex {re,im} as u64):
//   [0..3]    c0tot[l]   (all k=0 constant terms folded per l)
//   [4..19]   E[l*4 + (k-1)]  k=1..4   (a merged with b/c m=0)
//   [20..46]  B[l*9 + (m-1)*3 + (k-1)]  l<3, m=1..3, k=1..3
//   [47..73]  C[...same...]
constexpr int NCOEF = 74;

__global__ __launch_bounds__(TPB, 8)
void gmp_kernel(const float* __restrict__ xre, const float* __restrict__ xim,
                const float* __restrict__ a_re, const float* __restrict__ a_im,
                const float* __restrict__ b_re, const float* __restrict__ b_im,
                const float* __restrict__ c_re, const float* __restrict__ c_im,
                float* __restrict__ out, int N) {
    __shared__ u64 sX[PTILE];    // {re, im}
    __shared__ u64 sP1[PTILE];   // {p,  p }
    __shared__ u64 sP2[PTILE];   // {p2, p2}
    __shared__ u64 sP3[PTILE];   // {p3, p3}
    __shared__ float2 scoef[NCOEF];

    const int tid = threadIdx.x;
    const int blockStart = blockIdx.x * SPB;

    // ---- per-block coefficient merge (threads 0..73)
    if (tid < NCOEF) {
        float re, im;
        if (tid < 4) {                 // c0tot[l]
            int l = tid;
            re = a_re[l]; im = a_im[l];
            if (l < 3) {
#pragma unroll
                for (int m = 0; m < 4; ++m) {
                    re += b_re[l * 4 + m] + c_re[l * 4 + m];
                    im += b_im[l * 4 + m] + c_im[l * 4 + m];
                }
            }
        } else if (tid < 20) {         // E[l][k], k=1..4
            int e = tid - 4, l = e >> 2, k = (e & 3) + 1;
            re = a_re[k * 4 + l]; im = a_im[k * 4 + l];
            if (l < 3 && k < 4) {
                int src = (k * 3 + l) * 4;
                re += b_re[src] + c_re[src];
                im += b_im[src] + c_im[src];
            }
        } else if (tid < 47) {         // B
            int e = tid - 20, l = e / 9, r9 = e % 9, m = r9 / 3 + 1, k = r9 % 3 + 1;
            int src = (k * 3 + l) * 4 + m;
            re = b_re[src]; im = b_im[src];
        } else {                       // C
            int e = tid - 47, l = e / 9, r9 = e % 9, m = r9 / 3 + 1, k = r9 % 3 + 1;
            int src = (k * 3 + l) * 4 + m;
            re = c_re[src]; im = c_im[src];
        }
        scoef[tid] = make_float2(re, im);
    }

    // ---- cooperative tile: load once, compute powers once, padded stores
#pragma unroll
    for (int s = tid; s < TILE; s += TPB) {
        int g = blockStart - 5 + s;
        g = max(g, 0);
        g = min(g, N - 1);
        float r = xre[g];
        float i = xim[g];
        float p  = sqrt_approx(fmaf(r, r, i * i));
        float p2 = p * p;
        float p3 = p2 * p;
        int ps = s + (s >> 2);
        sX[ps]  = pack2(r, i);
        sP1[ps] = pack2(p, p);
        sP2[ps] = pack2(p2, p2);
        sP3[ps] = pack2(p3, p3);
    }
    __syncthreads();

    const u64* sc = reinterpret_cast<const u64*>(scoef);
    const int pb = tid * 5;          // pad(tid*4)
    const int n0 = blockStart + tid * ITER;

    // padded index for compile-time window offset j (0..11):
#define PIDX(j) (pb + (j) + ((j) >> 2))

    float yr[ITER], yi[ITER];
#pragma unroll
    for (int it = 0; it < ITER; ++it) { yr[it] = 0.f; yi[it] = 0.f; }

#pragma unroll
    for (int l = 0; l < 4; ++l) {
        u64 wA[ITER], wB[ITER];
        {
            const u64 c0 = sc[l];
#pragma unroll
            for (int it = 0; it < ITER; ++it) { wA[it] = c0; wB[it] = 0ull; }
        }
        // E (deg 4) at j = it - l + 5:
        //   e1*p + e2*p2 + e3*p3 + e4*p4, with e4*p4+e3*p3 = (e4*p+e3)*p3
        {
            const u64 e1 = sc[4 + l * 4 + 0], e2 = sc[4 + l * 4 + 1],
                      e3 = sc[4 + l * 4 + 2], e4 = sc[4 + l * 4 + 3];
#pragma unroll
            for (int it = 0; it < ITER; ++it) {
                const int j = it - l + 5;
                const u64 P1 = sP1[PIDX(j)];
                const u64 P2 = sP2[PIDX(j)];
                const u64 P3 = sP3[PIDX(j)];
                u64 s43 = fma2(e4, P1, e3);          // e4*p + e3
                wA[it] = fma2(e1, P1, wA[it]);
                wB[it] = fma2(e2, P2, wB[it]);
                wA[it] = fma2(s43, P3, wA[it]);      // + e3*p3 + e4*p4
            }
        }
        if (l < 3) {
#pragma unroll
            for (int m = 1; m < 4; ++m) {            // B at j = it - l - m + 5
                const int bb = 20 + l * 9 + (m - 1) * 3;
                const u64 b1 = sc[bb + 0], b2 = sc[bb + 1], b3 = sc[bb + 2];
#pragma unroll
                for (int it = 0; it < ITER; ++it) {
                    const int j = it - l - m + 5;
                    wA[it] = fma2(b1, sP1[PIDX(j)], wA[it]);
                    wB[it] = fma2(b2, sP2[PIDX(j)], wB[it]);
                    wA[it] = fma2(b3, sP3[PIDX(j)], wA[it]);
                }
            }
#pragma unroll
            for (int m = 1; m < 4; ++m) {            // C at j = it - l + m + 5
                const int cb = 47 + l * 9 + (m - 1) * 3;
                const u64 c1 = sc[cb + 0], c2 = sc[cb + 1], c3 = sc[cb + 2];
#pragma unroll
                for (int it = 0; it < ITER; ++it) {
                    const int j = it - l + m + 5;
                    wB[it] = fma2(c1, sP1[PIDX(j)], wB[it]);
                    wA[it] = fma2(c2, sP2[PIDX(j)], wA[it]);
                    wB[it] = fma2(c3, sP3[PIDX(j)], wB[it]);
                }
            }
        }
        // combine: y[n+it] += x[n+it-l] * (wA+wB)
#pragma unroll
        for (int it = 0; it < ITER; ++it) {
            u64 w = add2(wA[it], wB[it]);
            float vr, vi;
            unpack2(w, vr, vi);
            float r, i;
            unpack2(sX[PIDX(it - l + 5)], r, i);
            yr[it] = fmaf(r, vr, yr[it]);
            yr[it] = fmaf(-i, vi, yr[it]);
            yi[it] = fmaf(r, vi, yi[it]);
            yi[it] = fmaf(i, vr, yi[it]);
        }
    }
#undef PIDX

    if (n0 + ITER <= N) {
        *reinterpret_cast<float4*>(out + n0)     = make_float4(yr[0], yr[1], yr[2], yr[3]);
        *reinterpret_cast<float4*>(out + N + n0) = make_float4(yi[0], yi[1], yi[2], yi[3]);
    } else {
#pragma unroll
        for (int it = 0; it < ITER; ++it) {
            int n = n0 + it;
            if (n < N) { out[n] = yr[it]; out[N + n] = yi[it]; }
        }
    }
}

extern "C" void kernel_launch(void* const* d_in, const int* in_sizes, int n_in,
                              void* d_out, int out_size) {
    const float* x_re = (const float*)d_in[0];
    const float* x_im = (const float*)d_in[1];
    const float* a_re = (const float*)d_in[2];
    const float* a_im = (const float*)d_in[3];
    const float* b_re = (const float*)d_in[4];
    const float* b_im = (const float*)d_in[5];
    const float* c_re = (const float*)d_in[6];
    const float* c_im = (const float*)d_in[7];
    float* out = (float*)d_out;
    const int N = in_sizes[0];

    const int grid = (N + SPB - 1) / SPB;
    gmp_kernel<<<grid, TPB>>>(x_re, x_im, a_re, a_im, b_re, b_im,
                              c_re, c_im, out, N);
}

// round 7
// speedup vs baseline: 1.8209x; 1.8209x over previous
#include <cuda_runtime.h>
#include <cstdint>

// ---------------------------------------------------------------------------
// GMP_34196529611440 : generalized memory polynomial, single fused kernel.
// Round 6: Horner form (low register pressure, round-2-proven) +
//          conflict-free padded shared tile (round-5-proven) + ITER=8.
//   y[n] = sum_l x[n-l] * [ c0tot_l + E_l(p[n-l]) + sum_m B(p[n-l-m]) + C(p[n-l+m]) ]
//   k=0 constants folded into c0tot -> every poly is w = fma2(q, p, w).
// ---------------------------------------------------------------------------

typedef unsigned long long u64;

__device__ __forceinline__ u64 fma2(u64 a, u64 b, u64 c) {
    u64 d;
    asm("fma.rn.f32x2 %0, %1, %2, %3;" : "=l"(d) : "l"(a), "l"(b), "l"(c));
    return d;
}
__device__ __forceinline__ u64 pack2(float x, float y) {
    u64 r;
    asm("mov.b64 %0, {%1, %2};" : "=l"(r) : "f"(x), "f"(y));
    return r;
}
__device__ __forceinline__ void unpack2(u64 v, float& x, float& y) {
    asm("mov.b64 {%0, %1}, %2;" : "=f"(x), "=f"(y) : "l"(v));
}
__device__ __forceinline__ float sqrt_approx(float s) {
    float r;
    asm("sqrt.approx.f32 %0, %1;" : "=f"(r) : "f"(s));
    return r;
}

constexpr int ITER = 8;            // consecutive samples per thread
constexpr int TPB  = 128;
constexpr int SPB  = TPB * ITER;   // 1024 (divides N=2^20 exactly)
constexpr int TILE = SPB + 8;      // samples blockStart-5 .. blockStart+SPB+2
// pad(i) = i + (i>>3): element stride for a thread's window is 9 (odd)
// -> LDS.64 lane addresses hit distinct banks, conflict-free.
constexpr int PTILE = (TILE - 1) + ((TILE - 1) >> 3) + 1;

// shared coefficient layout (complex {re,im} as u64):
//   [0..3]    c0tot[l]   (all k=0 constant terms folded per l)
//   [4..19]   E[l*4 + (k-1)]  k=1..4   (a merged with b/c m=0 terms)
//   [20..46]  B[l*9 + (m-1)*3 + (k-1)]  l<3, m=1..3, k=1..3
//   [47..73]  C[...same...]
constexpr int NCOEF = 74;

__global__ __launch_bounds__(TPB, 4)
void gmp_kernel(const float* __restrict__ xre, const float* __restrict__ xim,
                const float* __restrict__ a_re, const float* __restrict__ a_im,
                const float* __restrict__ b_re, const float* __restrict__ b_im,
                const float* __restrict__ c_re, const float* __restrict__ c_im,
                float* __restrict__ out, int N) {
    __shared__ u64 sP[PTILE];      // {p, p}   duplicated |x|
    __shared__ u64 sX[PTILE];      // {re, im}
    __shared__ float2 scoef[NCOEF];

    const int tid = threadIdx.x;
    const int blockStart = blockIdx.x * SPB;

    // ---- per-block coefficient merge (threads 0..73)
    if (tid < NCOEF) {
        float re, im;
        if (tid < 4) {                 // c0tot[l]
            int l = tid;
            re = a_re[l]; im = a_im[l];
            if (l < 3) {
#pragma unroll
                for (int m = 0; m < 4; ++m) {
                    re += b_re[l * 4 + m] + c_re[l * 4 + m];
                    im += b_im[l * 4 + m] + c_im[l * 4 + m];
                }
            }
        } else if (tid < 20) {         // E[l][k], k=1..4
            int e = tid - 4, l = e >> 2, k = (e & 3) + 1;
            re = a_re[k * 4 + l]; im = a_im[k * 4 + l];
            if (l < 3 && k < 4) {      // merge b/c m=0
                int src = (k * 3 + l) * 4;
                re += b_re[src] + c_re[src];
                im += b_im[src] + c_im[src];
            }
        } else if (tid < 47) {         // B
            int e = tid - 20, l = e / 9, r9 = e % 9, m = r9 / 3 + 1, k = r9 % 3 + 1;
            int src = (k * 3 + l) * 4 + m;
            re = b_re[src]; im = b_im[src];
        } else {                       // C
            int e = tid - 47, l = e / 9, r9 = e % 9, m = r9 / 3 + 1, k = r9 % 3 + 1;
            int src = (k * 3 + l) * 4 + m;
            re = c_re[src]; im = c_im[src];
        }
        scoef[tid] = make_float2(re, im);
    }

    // ---- cooperative tile load: each sample once, |x| once, padded stores
    for (int s = tid; s < TILE; s += TPB) {
        int g = blockStart - 5 + s;
        g = max(g, 0);
        g = min(g, N - 1);
        float r = xre[g];
        float i = xim[g];
        float p = sqrt_approx(fmaf(r, r, i * i));
        int ps = s + (s >> 3);
        sX[ps] = pack2(r, i);
        sP[ps] = pack2(p, p);
    }
    __syncthreads();

    const u64* sc = reinterpret_cast<const u64*>(scoef);
    const int pb9 = tid * 9;            // pad(tid*8)
    const int n0 = blockStart + tid * ITER;

    // window j=0..15 corresponds to sample n0 + j - 5; padded index:
#define PIDX(j) (pb9 + (j) + ((j) >> 3))

    // |x| window in registers (16 u64, loaded once, heavy reuse)
    u64 pp2[ITER + 8];
#pragma unroll
    for (int j = 0; j < ITER + 8; ++j) pp2[j] = sP[PIDX(j)];

    float yr[ITER], yi[ITER];
#pragma unroll
    for (int it = 0; it < ITER; ++it) { yr[it] = 0.f; yi[it] = 0.f; }

#pragma unroll
    for (int l = 0; l < 4; ++l) {
        u64 wl[ITER];
        {
            const u64 c0 = sc[l];
#pragma unroll
            for (int it = 0; it < ITER; ++it) wl[it] = c0;
        }
        // E (deg 4): w += ((e4 p + e3) p + e2) p + e1) p  at p[n+it-l]
        {
            const u64 e1 = sc[4 + l * 4 + 0], e2 = sc[4 + l * 4 + 1],
                      e3 = sc[4 + l * 4 + 2], e4 = sc[4 + l * 4 + 3];
#pragma unroll
            for (int it = 0; it < ITER; ++it) {
                const u64 p = pp2[it - l + 5];
                u64 q = fma2(e4, p, e3);
                q = fma2(q, p, e2);
                q = fma2(q, p, e1);
                wl[it] = fma2(q, p, wl[it]);
            }
        }
        if (l < 3) {
#pragma unroll
            for (int m = 1; m < 4; ++m) {   // B at p[n+it-l-m]
                const int bb = 20 + l * 9 + (m - 1) * 3;
                const u64 b1 = sc[bb + 0], b2 = sc[bb + 1], b3 = sc[bb + 2];
#pragma unroll
                for (int it = 0; it < ITER; ++it) {
                    const u64 p = pp2[it - l - m + 5];
                    u64 q = fma2(b3, p, b2);
                    q = fma2(q, p, b1);
                    wl[it] = fma2(q, p, wl[it]);
                }
            }
#pragma unroll
            for (int m = 1; m < 4; ++m) {   // C at p[n+it-l+m]
                const int cb = 47 + l * 9 + (m - 1) * 3;
                const u64 c1 = sc[cb + 0], c2 = sc[cb + 1], c3 = sc[cb + 2];
#pragma unroll
                for (int it = 0; it < ITER; ++it) {
                    const u64 p = pp2[it - l + m + 5];
                    u64 q = fma2(c3, p, c2);
                    q = fma2(q, p, c1);
                    wl[it] = fma2(q, p, wl[it]);
                }
            }
        }
        // combine: y[n+it] += x[n+it-l] * w_l   (complex; x from shared)
#pragma unroll
        for (int it = 0; it < ITER; ++it) {
            float vr, vi;
            unpack2(wl[it], vr, vi);
            float r, i;
            unpack2(sX[PIDX(it - l + 5)], r, i);
            yr[it] = fmaf(r, vr, yr[it]);
            yr[it] = fmaf(-i, vi, yr[it]);
            yi[it] = fmaf(r, vi, yi[it]);
            yi[it] = fmaf(i, vr, yi[it]);
        }
    }
#undef PIDX

    // n0 is a multiple of 8 -> 32B-aligned float4 stores; SPB divides N
    if (n0 + ITER <= N) {
#pragma unroll
        for (int h = 0; h < ITER / 4; ++h) {
            *reinterpret_cast<float4*>(out + n0 + 4 * h) =
                make_float4(yr[4 * h], yr[4 * h + 1], yr[4 * h + 2], yr[4 * h + 3]);
            *reinterpret_cast<float4*>(out + N + n0 + 4 * h) =
                make_float4(yi[4 * h], yi[4 * h + 1], yi[4 * h + 2], yi[4 * h + 3]);
        }
    } else {
#pragma unroll
        for (int it = 0; it < ITER; ++it) {
            int n = n0 + it;
            if (n < N) { out[n] = yr[it]; out[N + n] = yi[it]; }
        }
    }
}

extern "C" void kernel_launch(void* const* d_in, const int* in_sizes, int n_in,
                              void* d_out, int out_size) {
    const float* x_re = (const float*)d_in[0];
    const float* x_im = (const float*)d_in[1];
    const float* a_re = (const float*)d_in[2];
    const float* a_im = (const float*)d_in[3];
    const float* b_re = (const float*)d_in[4];
    const float* b_im = (const float*)d_in[5];
    const float* c_re = (const float*)d_in[6];
    const float* c_im = (const float*)d_in[7];
    float* out = (float*)d_out;
    const int N = in_sizes[0];

    const int grid = (N + SPB - 1) / SPB;
    gmp_kernel<<<grid, TPB>>>(x_re, x_im, a_re, a_im, b_re, b_im,
                              c_re, c_im, out, N);
}

// round 8
// speedup vs baseline: 2.4461x; 1.3434x over previous
#include <cuda_runtime.h>
#include <cstdint>

// ---------------------------------------------------------------------------
// GMP_34196529611440 : generalized memory polynomial, single fused kernel.
// Round 8 = round 2 (best: Horner, ITER=4, TPB=256, 64 regs, occ 40%)
//           + round-5/7-proven conflict-free padded shared layout.
//   pad(i) = i + (i>>2); thread window stride = 5 u64 = 10 banks-words (odd/2)
//   -> every LDS.64 phase of 16 lanes covers 32 distinct banks.
// ---------------------------------------------------------------------------

typedef unsigned long long u64;

__device__ __forceinline__ u64 fma2(u64 a, u64 b, u64 c) {
    u64 d;
    asm("fma.rn.f32x2 %0, %1, %2, %3;" : "=l"(d) : "l"(a), "l"(b), "l"(c));
    return d;
}
__device__ __forceinline__ u64 pack2(float x, float y) {
    u64 r;
    asm("mov.b64 %0, {%1, %2};" : "=l"(r) : "f"(x), "f"(y));
    return r;
}
__device__ __forceinline__ void unpack2(u64 v, float& x, float& y) {
    asm("mov.b64 {%0, %1}, %2;" : "=f"(x), "=f"(y) : "l"(v));
}
__device__ __forceinline__ float sqrt_approx(float s) {
    float r;
    asm("sqrt.approx.f32 %0, %1;" : "=f"(r) : "f"(s));
    return r;
}

constexpr int ITER = 4;            // consecutive samples per thread
constexpr int TPB  = 256;
constexpr int SPB  = TPB * ITER;   // 1024 (divides N = 2^20)
constexpr int TILE = SPB + 12;     // samples blockStart-5 .. blockStart+SPB+6
// pad(i) = i + (i>>2)
constexpr int PTILE = (TILE - 1) + ((TILE - 1) >> 2) + 1;   // 1289

// shared coefficient layout (complex {re,im} as u64):
//   [0..3]    c0tot[l]   (all k=0 constant terms folded per l)
//   [4..19]   E[l*4 + (k-1)]  k=1..4   (a merged with b/c m=0 terms)
//   [20..46]  B[l*9 + (m-1)*3 + (k-1)]  l<3, m=1..3, k=1..3
//   [47..73]  C[...same...]
constexpr int NCOEF = 74;

__global__ __launch_bounds__(TPB, 4)
void gmp_kernel(const float* __restrict__ xre, const float* __restrict__ xim,
                const float* __restrict__ a_re, const float* __restrict__ a_im,
                const float* __restrict__ b_re, const float* __restrict__ b_im,
                const float* __restrict__ c_re, const float* __restrict__ c_im,
                float* __restrict__ out, int N) {
    __shared__ u64 sP[PTILE];      // {p, p}   duplicated |x|
    __shared__ u64 sX[PTILE];      // {re, im}
    __shared__ float2 scoef[NCOEF];

    const int tid = threadIdx.x;
    const int blockStart = blockIdx.x * SPB;

    // ---- per-block coefficient merge (threads 0..73), cheap one-time work
    if (tid < NCOEF) {
        float re, im;
        if (tid < 4) {                 // c0tot[l]
            int l = tid;
            re = a_re[l]; im = a_im[l];
            if (l < 3) {
#pragma unroll
                for (int m = 0; m < 4; ++m) {
                    re += b_re[l * 4 + m] + c_re[l * 4 + m];
                    im += b_im[l * 4 + m] + c_im[l * 4 + m];
                }
            }
        } else if (tid < 20) {         // E[l][k], k=1..4
            int e = tid - 4, l = e >> 2, k = (e & 3) + 1;
            re = a_re[k * 4 + l]; im = a_im[k * 4 + l];
            if (l < 3 && k < 4) {      // merge b/c m=0
                int src = (k * 3 + l) * 4;
                re += b_re[src] + c_re[src];
                im += b_im[src] + c_im[src];
            }
        } else if (tid < 47) {         // B
            int e = tid - 20, l = e / 9, r9 = e % 9, m = r9 / 3 + 1, k = r9 % 3 + 1;
            int src = (k * 3 + l) * 4 + m;
            re = b_re[src]; im = b_im[src];
        } else {                       // C
            int e = tid - 47, l = e / 9, r9 = e % 9, m = r9 / 3 + 1, k = r9 % 3 + 1;
            int src = (k * 3 + l) * 4 + m;
            re = c_re[src]; im = c_im[src];
        }
        scoef[tid] = make_float2(re, im);
    }

    // ---- cooperative tile load: each sample once, |x| once, padded stores
#pragma unroll
    for (int s = tid; s < TILE; s += TPB) {
        int g = blockStart - 5 + s;
        g = max(g, 0);
        g = min(g, N - 1);
        float r = xre[g];
        float i = xim[g];
        float p = sqrt_approx(fmaf(r, r, i * i));
        int ps = s + (s >> 2);
        sX[ps] = pack2(r, i);
        sP[ps] = pack2(p, p);
    }
    __syncthreads();

    const u64* sc = reinterpret_cast<const u64*>(scoef);
    const int pb5 = tid * 5;            // pad(tid*4)
    const int n0 = blockStart + tid * ITER;

    // window j = 0..11 corresponds to sample n0 + j - 5; padded index:
#define PIDX(j) (pb5 + (j) + ((j) >> 2))

    // |x| window in registers (12 u64, conflict-free loads, heavy reuse)
    u64 pp2[12];
#pragma unroll
    for (int j = 0; j < 12; ++j) pp2[j] = sP[PIDX(j)];

    float yr[ITER], yi[ITER];
#pragma unroll
    for (int it = 0; it < ITER; ++it) { yr[it] = 0.f; yi[it] = 0.f; }

#pragma unroll
    for (int l = 0; l < 4; ++l) {
        u64 wl[ITER];
        {
            const u64 c0 = sc[l];
#pragma unroll
            for (int it = 0; it < ITER; ++it) wl[it] = c0;
        }
        // E (deg 4): w += (((e4 p + e3) p + e2) p + e1) p   at p[n+it-l]
        {
            const u64 e1 = sc[4 + l * 4 + 0], e2 = sc[4 + l * 4 + 1],
                      e3 = sc[4 + l * 4 + 2], e4 = sc[4 + l * 4 + 3];
#pragma unroll
            for (int it = 0; it < ITER; ++it) {
                const u64 p = pp2[it - l + 5];
                u64 q = fma2(e4, p, e3);
                q = fma2(q, p, e2);
                q = fma2(q, p, e1);
                wl[it] = fma2(q, p, wl[it]);
            }
        }
        if (l < 3) {
#pragma unroll
            for (int m = 1; m < 4; ++m) {   // B at p[n+it-l-m]
                const int bb = 20 + l * 9 + (m - 1) * 3;
                const u64 b1 = sc[bb + 0], b2 = sc[bb + 1], b3 = sc[bb + 2];
#pragma unroll
                for (int it = 0; it < ITER; ++it) {
                    const u64 p = pp2[it - l - m + 5];
                    u64 q = fma2(b3, p, b2);
                    q = fma2(q, p, b1);
                    wl[it] = fma2(q, p, wl[it]);
                }
            }
#pragma unroll
            for (int m = 1; m < 4; ++m) {   // C at p[n+it-l+m]
                const int cb = 47 + l * 9 + (m - 1) * 3;
                const u64 c1 = sc[cb + 0], c2 = sc[cb + 1], c3 = sc[cb + 2];
#pragma unroll
                for (int it = 0; it < ITER; ++it) {
                    const u64 p = pp2[it - l + m + 5];
                    u64 q = fma2(c3, p, c2);
                    q = fma2(q, p, c1);
                    wl[it] = fma2(q, p, wl[it]);
                }
            }
        }
        // combine: y[n+it] += x[n+it-l] * w_l   (complex; x from padded shared)
#pragma unroll
        for (int it = 0; it < ITER; ++it) {
            float vr, vi;
            unpack2(wl[it], vr, vi);
            float r, i;
            unpack2(sX[PIDX(it - l + 5)], r, i);
            yr[it] = fmaf(r, vr, yr[it]);
            yr[it] = fmaf(-i, vi, yr[it]);
            yi[it] = fmaf(r, vi, yi[it]);
            yi[it] = fmaf(i, vr, yi[it]);
        }
    }
#undef PIDX

    // n0 is a multiple of 4 -> 16B-aligned float4 stores; SPB divides N
    if (n0 + ITER <= N) {
        *reinterpret_cast<float4*>(out + n0)     = make_float4(yr[0], yr[1], yr[2], yr[3]);
        *reinterpret_cast<float4*>(out + N + n0) = make_float4(yi[0], yi[1], yi[2], yi[3]);
    } else {
#pragma unroll
        for (int it = 0; it < ITER; ++it) {
            int n = n0 + it;
            if (n < N) { out[n] = yr[it]; out[N + n] = yi[it]; }
        }
    }
}

extern "C" void kernel_launch(void* const* d_in, const int* in_sizes, int n_in,
                              void* d_out, int out_size) {
    const float* x_re = (const float*)d_in[0];
    const float* x_im = (const float*)d_in[1];
    const float* a_re = (const float*)d_in[2];
    const float* a_im = (const float*)d_in[3];
    const float* b_re = (const float*)d_in[4];
    const float* b_im = (const float*)d_in[5];
    const float* c_re = (const float*)d_in[6];
    const float* c_im = (const float*)d_in[7];
    float* out = (float*)d_out;
    const int N = in_sizes[0];

    const int grid = (N + SPB - 1) / SPB;
    gmp_kernel<<<grid, TPB>>>(x_re, x_im, a_re, a_im, b_re, b_im,
                              c_re, c_im, out, N);
}